// round 10
// baseline (speedup 1.0000x reference)
#include <cuda_runtime.h>
#include <math_constants.h>

// MiniRocket round 10: IDENTICAL compute to round 9 (best main kernel), plus
// five no-op launches ahead of mr_main so ncu's "-s 5 -c 1" finally captures
// mr_main instead of mr_fin. Pure observability round (~+4us accepted).

#define NCH    8
#define LEN    1024
#define NKER   84
#define HALO   32
#define PITCHX 592
#define PITCHS 528
#define TOTF   9996

// [i][n][slot(3)][j][32] partial counts (negative); every read slot is
// rewritten each launch (slot2 only exists for i=0, fin reads it only there).
__device__ __align__(16) int g_part[4 * 64 * 3 * NKER * 32];

__device__ __forceinline__ int fset_gt(float a, float b)
{
    int m;   // 0xFFFFFFFF if a > b else 0
    asm("set.gt.s32.f32 %0, %1, %2;" : "=r"(m) : "f"(a), "f"(b));
    return m;
}

// order-preserving float -> uint key (monotone; -inf lowest, +inf highest)
__device__ __forceinline__ unsigned fkey(float x)
{
    int b = __float_as_int(x);
    return (unsigned)(b ^ ((b >> 31) | 0x80000000));
}

__global__ void mr_noop() {}

// ---------------------------------------------------------------------------
__global__ __launch_bounds__(128, 4)
void mr_main(const float* __restrict__ x,
             const float* __restrict__ biases,
             const int* __restrict__ ci)
{
    __shared__ __align__(16) float Xq[NCH * PITCHX];
    __shared__ __align__(16) float Sq[NCH * PITCHS];
    __shared__ float bsh[NKER * 30];
    __shared__ int comb[NKER];

    const int tid = threadIdx.x, warp = tid >> 5, lane = tid & 31;

    // block -> (dilation i, sample n, segment [ls, ls+seglen), slot)
    int bid = blockIdx.x;
    int i, n, ls, seglen, slot;
    if (bid < 192) {                       // i = 0: thirds (scalar path)
        i = 0; n = bid / 3; slot = bid - n * 3;
        ls = slot * 342;
        seglen = (slot == 2) ? 340 : 342;
    } else {                               // i >= 1: halves (vector path)
        int r = bid - 192;
        i = 1 + (r >> 7);
        int rr = r & 127;
        n = rr >> 1; slot = rr & 1;
        ls = slot * 512; seglen = 512;
    }
    const int d = 1 << i, p = 4 * d;
    const int nf = (i == 3) ? 29 : 30;

    if (tid < NKER) {                      // 84 lexicographic triples of 0..8
        int t = 0, val = 0;
        for (int a = 0; a < 9; a++)
            for (int b2 = a + 1; b2 < 9; b2++)
                for (int c2 = b2 + 1; c2 < 9; c2++) {
                    if (t == tid) val = a | (b2 << 8) | (c2 << 16);
                    t++;
                }
        comb[tid] = val;
    }
    for (int k = tid; k < NKER * nf; k += 128)
        bsh[k] = biases[i * 2520 + k];

    // stage padded segment of x[n]
    for (int c = 0; c < NCH; c++) {
        const float* xc = x + (n * NCH + c) * LEN;
        for (int u = tid; u < seglen + 2 * HALO; u += 128) {
            int l = ls - HALO + u;
            Xq[c * PITCHX + u] = (l >= 0 && l < LEN) ? xc[l] : 0.0f;
        }
    }
    __syncthreads();
    // per-channel 9-tap dilated sums
    for (int c = 0; c < NCH; c++) {
        const float* xb = Xq + c * PITCHX + HALO;
        float* sc = Sq + c * PITCHS;
        for (int u = tid; u < seglen; u += 128) {
            float s = ((xb[u-4*d] + xb[u-3*d]) + (xb[u-2*d] + xb[u-d]))
                    + ((xb[u] + xb[u+d]) + (xb[u+2*d] + xb[u+3*d])) + xb[u+4*d];
            sc[u] = s;
        }
    }
    __syncthreads();

    const int nstrip = (seglen + 127) >> 7;   // 128-position strips

    for (int jj = 0; jj < 21; jj++) {         // each warp owns 21 kernels
        const int j = warp * 21 + jj;
        const int cm = comb[j];
        const int da = (((cm      ) & 255) - 4) * d;
        const int db = (((cm >>  8) & 255) - 4) * d;
        const int dc = (((cm >> 16) & 255) - 4) * d;
        const int* cp = ci + (i * NKER + j) * 3;
        const int c0 = cp[0], c1 = cp[1], c2 = cp[2];
        const float* X0 = Xq + c0 * PITCHX + HALO;
        const float* X1 = Xq + c1 * PITCHX + HALO;
        const float* X2 = Xq + c2 * PITCHX + HALO;
        const float* S0 = Sq + c0 * PITCHS;
        const float* S1 = Sq + c1 * PITCHS;
        const float* S2 = Sq + c2 * PITCHS;

        int vlo = 0, vhi = seglen;
        if ((i + j) & 1) {                    // odd parity: interior [p, L-p)
            vlo = max(0, p - ls);
            vhi = min(seglen, LEN - p - ls);
        }
        const unsigned lim = (unsigned)max(0, vhi - vlo);  // clamp (R4 bug)

        // features 0..14 -> float compares (fma pipe)
        // features 15..29 -> uint-key compares (alu pipe)
        float    bvf[15];
        unsigned kbv[15];
        int      cf[15], cn[15];
        const float* bp = bsh + j * nf;
        #pragma unroll
        for (int f = 0; f < 15; f++) {
            bvf[f] = (f < nf) ? bp[f] : CUDART_INF_F;
            float bi = (f + 15 < nf) ? bp[f + 15] : CUDART_INF_F;
            kbv[f] = fkey(bi);
            cf[f] = 0; cn[f] = 0;
        }

        for (int st = 0; st < nstrip; st++) {
            const int base = st << 7;
            float cs[4];
            if (i == 0) {                     // scalar (odd tap offsets)
                #pragma unroll
                for (int k = 0; k < 4; k++) {
                    const int u = base + lane + 32 * k;
                    float a = ((X0[u+da] + X0[u+db]) + (X0[u+dc] + X1[u+da]))
                            + ((X1[u+db] + X1[u+dc]) + (X2[u+da] + X2[u+db]))
                            + X2[u+dc];
                    float c = fmaf(3.0f, a, -(S0[u] + S1[u] + S2[u]));
                    if ((unsigned)(u - vlo) >= lim) c = -CUDART_INF_F;
                    cs[k] = c;
                }
            } else {                          // float2 (even offsets, aligned)
                #pragma unroll
                for (int k = 0; k < 2; k++) {
                    const int u0 = base + 2 * lane + 64 * k;
                    float2 a0 = *(const float2*)(X0 + u0 + da);
                    float2 a1 = *(const float2*)(X0 + u0 + db);
                    float2 a2 = *(const float2*)(X0 + u0 + dc);
                    float2 a3 = *(const float2*)(X1 + u0 + da);
                    float2 a4 = *(const float2*)(X1 + u0 + db);
                    float2 a5 = *(const float2*)(X1 + u0 + dc);
                    float2 a6 = *(const float2*)(X2 + u0 + da);
                    float2 a7 = *(const float2*)(X2 + u0 + db);
                    float2 a8 = *(const float2*)(X2 + u0 + dc);
                    float2 s0 = *(const float2*)(S0 + u0);
                    float2 s1 = *(const float2*)(S1 + u0);
                    float2 s2 = *(const float2*)(S2 + u0);
                    float ax = ((a0.x+a1.x)+(a2.x+a3.x)) + ((a4.x+a5.x)+(a6.x+a7.x)) + a8.x;
                    float ay = ((a0.y+a1.y)+(a2.y+a3.y)) + ((a4.y+a5.y)+(a6.y+a7.y)) + a8.y;
                    float cx = fmaf(3.0f, ax, -(s0.x + s1.x + s2.x));
                    float cy = fmaf(3.0f, ay, -(s0.y + s1.y + s2.y));
                    const unsigned q0 = (unsigned)(u0 - vlo);
                    if (q0 >= lim)      cx = -CUDART_INF_F;
                    if (q0 + 1u >= lim) cy = -CUDART_INF_F;
                    cs[2*k]   = cx;
                    cs[2*k+1] = cy;
                }
            }
            const unsigned k0 = fkey(cs[0]), k1 = fkey(cs[1]);
            const unsigned k2 = fkey(cs[2]), k3 = fkey(cs[3]);
            // register-only compare phase, split across fma and alu pipes
            #pragma unroll
            for (int f = 0; f < 15; f++) {
                cf[f] += fset_gt(cs[0], bvf[f]) + fset_gt(cs[1], bvf[f]);
                cf[f] += fset_gt(cs[2], bvf[f]) + fset_gt(cs[3], bvf[f]);
                cn[f] += (int)(k0 > kbv[f]) + (int)(k1 > kbv[f]);
                cn[f] += (int)(k2 > kbv[f]) + (int)(k3 > kbv[f]);
            }
        }

        #pragma unroll
        for (int f = 0; f < 15; f++) {
            cf[f] = __reduce_add_sync(0xffffffffu, cf[f]);   // negative
            cn[f] = __reduce_add_sync(0xffffffffu, cn[f]);   // positive
        }

        if (lane == 0) {                      // plain stores to fixed slot
            int out30[30];
            #pragma unroll
            for (int f = 0; f < 15; f++) {
                out30[f]      = cf[f];        // already negative
                out30[f + 15] = -cn[f];       // store negative
            }
            int* dst = g_part + (((i * 64 + n) * 3 + slot) * NKER + j) * 32;
            #pragma unroll
            for (int w = 0; w < 7; w++)
                *reinterpret_cast<int4*>(dst + w * 4) =
                    make_int4(out30[w*4], out30[w*4+1], out30[w*4+2], out30[w*4+3]);
            dst[28] = out30[28];
            dst[29] = out30[29];
        }
    }
}

// ---------------------------------------------------------------------------
// sum fixed slots, scale, scatter; no divides, no writes back to g_part.
__global__ void mr_fin(float* __restrict__ out)
{
    const int j = blockIdx.x;                 // 84
    const int i = blockIdx.y;                 // 4
    const int n = blockIdx.z * 8 + threadIdx.y;
    const int f = threadIdx.x;                // 30
    const int nf = (i == 3) ? 29 : 30;
    if (f >= nf) return;

    const int base = (((i * 64 + n) * 3) * NKER + j) * 32 + f;
    const int ss   = NKER * 32;               // slot stride
    int c = g_part[base] + g_part[base + ss];
    if (i == 0) c += g_part[base + 2 * ss];   // thirds

    const float inv = (((i + j) & 1) == 0)
                    ? (1.0f / 1024.0f)
                    : (1.0f / (1024.0f - 8.0f * (float)(1 << i)));
    out[n * TOTF + i * 2520 + j * nf + f] = (float)(-c) * inv;
}

// ---------------------------------------------------------------------------
extern "C" void kernel_launch(void* const* d_in, const int* in_sizes, int n_in,
                              void* d_out, int out_size)
{
    const float* x  = (const float*)d_in[0];
    const float* b  = (const float*)d_in[1];
    const int*   ci = (const int*)d_in[2];
    float* out = (float*)d_out;

    cudaFuncSetAttribute(mr_main,
                         cudaFuncAttributePreferredSharedMemoryCarveout, 100);

    // Five no-op launches: process launch index 5 (ncu -s 5 -c 1) becomes
    // mr_main instead of mr_fin. Observability; ~3-5us overhead.
    mr_noop<<<1, 32>>>();
    mr_noop<<<1, 32>>>();
    mr_noop<<<1, 32>>>();
    mr_noop<<<1, 32>>>();
    mr_noop<<<1, 32>>>();

    mr_main<<<576, 128>>>(x, b, ci);
    mr_fin<<<dim3(NKER, 4, 8), dim3(30, 8)>>>(out);
}

// round 11
// speedup vs baseline: 1.0513x; 1.0513x over previous
#include <cuda_runtime.h>
#include <math_constants.h>

// MiniRocket round 11: rank-bucket (histogram) PPV — the measured-fastest
// main design (R3, ~110us) with: 4-deep ILP on the rank chains, 5 blocks/SM
// (740 = 148x5 exact wave), in-block bias sort, fixed-slot stores (no
// atomics, no re-zero), and a 3-launch order so ncu captures mr_main.

#define NCH    8
#define LEN    1024
#define NKER   84
#define HALO   32
#define PITCHX 448
#define PITCHS 384
#define TOTF   9996
#define SLOTS  5

// [i][n][slot][j][32] partial counts. Zero-initialized at module load;
// slots never written by the (deterministic) writers stay 0 forever.
__device__ __align__(16) int g_part[4 * 64 * SLOTS * NKER * 32];

__global__ void mr_noop() {}

// count of sorted entries < c   (5-step branchless lower bound over 32)
__device__ __forceinline__ int rank32(const float* __restrict__ sb, float c)
{
    int lo = (c > sb[15]) ? 16 : 0;
    lo += (c > sb[lo + 7]) ? 8 : 0;
    lo += (c > sb[lo + 3]) ? 4 : 0;
    lo += (c > sb[lo + 1]) ? 2 : 0;
    lo += (c > sb[lo])     ? 1 : 0;
    return lo;
}

// ---------------------------------------------------------------------------
__global__ __launch_bounds__(128, 5)
void mr_main(const float* __restrict__ x,
             const float* __restrict__ biases,
             const int* __restrict__ ci)
{
    __shared__ __align__(16) float Xq[NCH * PITCHX];
    __shared__ __align__(16) float Sq[NCH * PITCHS];
    __shared__ float sb[NKER * 32];            // sorted biases per kernel
    __shared__ unsigned char sp[NKER * 32];    // sort permutation
    __shared__ unsigned char hist[4 * 32 * 36];// [warp][lane] private rows
    __shared__ int comb[NKER];

    const int tid = threadIdx.x, warp = tid >> 5, lane = tid & 31;

    // block -> (dilation, local block, range): 200 + 3*180 = 740 = 148*5.
    int bid = blockIdx.x;
    int i, bl, R;
    if (bid < 200) { i = 0; bl = bid; R = 328; }
    else { int r = bid - 200; i = 1 + r / 180; bl = r % 180; R = 365; }
    const int d = 1 << i, p = 4 * d;
    const int nf = (i == 3) ? 29 : 30;

    if (tid < NKER) {                      // 84 lexicographic triples of 0..8
        int t = 0, val = 0;
        for (int a = 0; a < 9; a++)
            for (int b2 = a + 1; b2 < 9; b2++)
                for (int c2 = b2 + 1; c2 < 9; c2++) {
                    if (t == tid) val = a | (b2 << 8) | (c2 << 16);
                    t++;
                }
        comb[tid] = val;
    }

    // in-block bias sort: each warp sorts its own 21 kernels' 30 biases
    // (pad to 32 with +inf) via all-pairs shfl ranking.
    for (int jj = 0; jj < 21; jj++) {
        const int j = warp * 21 + jj;
        float v = (lane < nf) ? biases[i * 2520 + j * nf + lane] : CUDART_INF_F;
        int rank = 0;
        #pragma unroll
        for (int k = 1; k < 32; k++) {
            float ov = __shfl_xor_sync(0xffffffffu, v, k);
            int o = lane ^ k;
            rank += (ov < v || (ov == v && o < lane)) ? 1 : 0;
        }
        sb[j * 32 + rank] = v;
        sp[j * 32 + rank] = (unsigned char)lane;
    }
    __syncwarp();

    const int g0 = bl * R;
    const int g1 = min(g0 + R, 65536);
    int g = g0;
    while (g < g1) {                       // <= 2 sample-segments per block
        const int n = g >> 10;
        const int ls = g & 1023;
        const int seglen = min(LEN - ls, g1 - g);
        const int slot = bl - (n << 10) / R;   // fixed slot, 0..SLOTS-1

        __syncthreads();
        for (int c = 0; c < NCH; c++) {    // stage padded segment of x[n]
            const float* xc = x + (n * NCH + c) * LEN;
            for (int u = tid; u < seglen + 2 * HALO; u += 128) {
                int l = ls - HALO + u;
                Xq[c * PITCHX + u] = (l >= 0 && l < LEN) ? xc[l] : 0.0f;
            }
        }
        __syncthreads();
        for (int c = 0; c < NCH; c++) {    // per-channel 9-tap dilated sums
            const float* xb = Xq + c * PITCHX + HALO;
            float* sc = Sq + c * PITCHS;
            for (int u = tid; u < seglen; u += 128) {
                float s = ((xb[u-4*d] + xb[u-3*d]) + (xb[u-2*d] + xb[u-d]))
                        + ((xb[u] + xb[u+d]) + (xb[u+2*d] + xb[u+3*d])) + xb[u+4*d];
                sc[u] = s;
            }
        }
        __syncthreads();

        unsigned char* hrow  = hist + (warp * 32 + lane) * 36;
        unsigned char* hwarp = hist + warp * 32 * 36;

        for (int jj = 0; jj < 21; jj++) {  // each warp owns 21 kernels
            const int j = warp * 21 + jj;
            const int cm = comb[j];
            const int da = (((cm      ) & 255) - 4) * d;
            const int db = (((cm >>  8) & 255) - 4) * d;
            const int dc = (((cm >> 16) & 255) - 4) * d;
            const int* cp = ci + (i * NKER + j) * 3;
            const int c0 = cp[0], c1 = cp[1], c2 = cp[2];
            const float* X0 = Xq + c0 * PITCHX + HALO;
            const float* X1 = Xq + c1 * PITCHX + HALO;
            const float* X2 = Xq + c2 * PITCHX + HALO;
            const float* S0 = Sq + c0 * PITCHS;
            const float* S1 = Sq + c1 * PITCHS;
            const float* S2 = Sq + c2 * PITCHS;
            const float* sbj = sb + j * 32;

            int vlo = 0, vhi = seglen;
            if ((i + j) & 1) {             // odd parity: interior [p, L-p)
                vlo = max(0, p - ls);
                vhi = min(seglen, LEN - p - ls);
            }

            __syncwarp();                  // prior epilogue reads done
            #pragma unroll
            for (int t = 0; t < 9; t++)
                *(unsigned*)(hrow + 4 * t) = 0u;

            // 4 positions in flight per iteration (128-position strips)
            for (int bse = 0; bse < seglen; bse += 128) {
                float cs[4]; int uu[4];
                if (i == 0) {              // d=1: odd tap offsets -> scalar
                    #pragma unroll
                    for (int k = 0; k < 4; k++) {
                        const int u = bse + lane + 32 * k;
                        uu[k] = u;
                        float a = ((X0[u+da] + X0[u+db]) + (X0[u+dc] + X1[u+da]))
                                + ((X1[u+db] + X1[u+dc]) + (X2[u+da] + X2[u+db]))
                                + X2[u+dc];
                        cs[k] = fmaf(3.0f, a, -(S0[u] + S1[u] + S2[u]));
                    }
                } else {                   // even d: float2, aligned
                    #pragma unroll
                    for (int k = 0; k < 2; k++) {
                        const int u0 = bse + 2 * lane + 64 * k;
                        float2 a0 = *(const float2*)(X0 + u0 + da);
                        float2 a1 = *(const float2*)(X0 + u0 + db);
                        float2 a2 = *(const float2*)(X0 + u0 + dc);
                        float2 a3 = *(const float2*)(X1 + u0 + da);
                        float2 a4 = *(const float2*)(X1 + u0 + db);
                        float2 a5 = *(const float2*)(X1 + u0 + dc);
                        float2 a6 = *(const float2*)(X2 + u0 + da);
                        float2 a7 = *(const float2*)(X2 + u0 + db);
                        float2 a8 = *(const float2*)(X2 + u0 + dc);
                        float2 s0 = *(const float2*)(S0 + u0);
                        float2 s1 = *(const float2*)(S1 + u0);
                        float2 s2 = *(const float2*)(S2 + u0);
                        float ax = ((a0.x+a1.x)+(a2.x+a3.x)) + ((a4.x+a5.x)+(a6.x+a7.x)) + a8.x;
                        float ay = ((a0.y+a1.y)+(a2.y+a3.y)) + ((a4.y+a5.y)+(a6.y+a7.y)) + a8.y;
                        cs[2*k]   = fmaf(3.0f, ax, -(s0.x + s1.x + s2.x));
                        cs[2*k+1] = fmaf(3.0f, ay, -(s0.y + s1.y + s2.y));
                        uu[2*k]   = u0;
                        uu[2*k+1] = u0 + 1;
                    }
                }
                // 4 independent rank chains, then predicated bumps
                int r0 = rank32(sbj, cs[0]);
                int r1 = rank32(sbj, cs[1]);
                int r2 = rank32(sbj, cs[2]);
                int r3 = rank32(sbj, cs[3]);
                if (uu[0] >= vlo && uu[0] < vhi) hrow[r0]++;
                if (uu[1] >= vlo && uu[1] < vhi) hrow[r1]++;
                if (uu[2] >= vlo && uu[2] < vhi) hrow[r2]++;
                if (uu[3] >= vlo && uu[3] < vhi) hrow[r3]++;
            }

            __syncwarp();                  // all rows written
            // bin `lane` summed over the 32 private rows (diagonal walk)
            int tot = 0;
            #pragma unroll
            for (int t = 0; t < 32; t++) {
                int l = (lane + t) & 31;
                tot += hwarp[l * 36 + lane];
            }
            // suffix scan: suf[k] = sum_{r>=k} tot[r]
            int suf = tot;
            #pragma unroll
            for (int s = 1; s < 32; s <<= 1) {
                int v = __shfl_down_sync(0xffffffffu, suf, s);
                if (lane < 32 - s) suf += v;
            }
            int cnts = __shfl_down_sync(0xffffffffu, suf, 1); // lane s -> suf[s+1]
            if (lane < nf && cnts > 0) {
                int f = sp[j * 32 + lane];                    // original order
                g_part[(((i * 64 + n) * SLOTS + slot) * NKER + j) * 32 + f] = cnts;
            }
        }
        g += seglen;
    }
}

// ---------------------------------------------------------------------------
// sum the fixed slots, scale, scatter; unwritten slots are permanently 0.
__global__ void mr_fin(float* __restrict__ out)
{
    const int j = blockIdx.x;                 // 84
    const int i = blockIdx.y;                 // 4
    const int n = blockIdx.z * 8 + threadIdx.y;
    const int f = threadIdx.x;                // 30
    const int nf = (i == 3) ? 29 : 30;
    if (f >= nf) return;

    const int base = ((i * 64 + n) * SLOTS * NKER + j) * 32 + f;
    const int ss   = NKER * 32;               // slot stride
    int c = 0;
    #pragma unroll
    for (int s = 0; s < SLOTS; s++) c += g_part[base + s * ss];

    const float inv = (((i + j) & 1) == 0)
                    ? (1.0f / 1024.0f)
                    : (1.0f / (1024.0f - 8.0f * (float)(1 << i)));
    out[n * TOTF + i * 2520 + j * nf + f] = (float)c * inv;
}

// ---------------------------------------------------------------------------
extern "C" void kernel_launch(void* const* d_in, const int* in_sizes, int n_in,
                              void* d_out, int out_size)
{
    const float* x  = (const float*)d_in[0];
    const float* b  = (const float*)d_in[1];
    const int*   ci = (const int*)d_in[2];
    float* out = (float*)d_out;

    cudaFuncSetAttribute(mr_main,
                         cudaFuncAttributePreferredSharedMemoryCarveout, 100);

    // 3 launches: ncu's skip-5 capture lands on launch #1 of the call
    // (empirically: 2-launch calls capture #2, 3-launch calls capture #1).
    mr_main<<<740, 128>>>(x, b, ci);
    mr_fin<<<dim3(NKER, 4, 8), dim3(30, 8)>>>(out);
    mr_noop<<<1, 32>>>();
}

// round 13
// speedup vs baseline: 1.2278x; 1.1679x over previous
#include <cuda_runtime.h>
#include <math_constants.h>

// MiniRocket round 13: round-12 with the combination-unranking bug fixed
// (second-element loop count is 8-b2, not 9-b2). Design: histogram PPV,
// 42.3KB smem -> true 5 blocks/SM, 684 blocks = one wave, rank tree with
// 3 register levels + 2 LDS levels.

#define NCH    8
#define LEN    1024
#define NKER   84
#define HALO   32
#define RNG    384
#define PITCHX 448            // RNG + 2*HALO
#define PITCHS 384
#define TOTF   9996
#define SLOTS  4

// [i][n][slot][j][32] partial counts; zero-init at load; slots never written
// by the deterministic writers stay 0 forever.
__device__ __align__(16) int g_part[4 * 64 * SLOTS * NKER * 32];

__global__ void mr_noop() {}

// ---------------------------------------------------------------------------
__global__ __launch_bounds__(128, 5)
void mr_main(const float* __restrict__ x,
             const float* __restrict__ biases,
             const int* __restrict__ ci)
{
    __shared__ __align__(16) float Xq[NCH * PITCHX];   // 14336 B
    __shared__ __align__(16) float Sq[NCH * PITCHS];   // 12288 B
    __shared__ float sb[NKER * 31];                    // 10416 B sorted biases
    __shared__ unsigned sp[NKER * 5];                  //  1680 B packed perm
    __shared__ unsigned char hist[4 * 32 * 36];        //  4608 B

    const int tid = threadIdx.x, warp = tid >> 5, lane = tid & 31;

    // dilations interleaved across consecutive blocks for SM-level mixing
    const int bid = blockIdx.x;
    const int i  = bid & 3;
    const int bl = bid >> 2;              // 0..170
    const int d = 1 << i, p = 4 * d;
    const int nf = (i == 3) ? 29 : 30;

    // in-block bias sort (all-pairs shfl rank); perm packed 5-bit x 6/word.
    unsigned char* scr = hist + warp * 32 * 36;   // warp-private scratch
    for (int jj = 0; jj < 21; jj++) {
        const int j = warp * 21 + jj;
        float v = (lane < nf) ? biases[i * 2520 + j * nf + lane] : CUDART_INF_F;
        int rank = 0;
        #pragma unroll
        for (int k = 1; k < 32; k++) {
            float ov = __shfl_xor_sync(0xffffffffu, v, k);
            int o = lane ^ k;
            rank += (ov < v || (ov == v && o < lane)) ? 1 : 0;
        }
        if (rank < 31) sb[j * 31 + rank] = v;
        if (rank < 30) scr[rank] = (unsigned char)lane;
        __syncwarp();
        if (lane < 5) {
            unsigned w = 0;
            #pragma unroll
            for (int e = 0; e < 6; e++)
                w |= (unsigned)scr[lane * 6 + e] << (5 * e);
            sp[j * 5 + lane] = w;
        }
        __syncwarp();
    }

    const int g0 = bl * RNG;
    const int g1 = min(g0 + RNG, 65536);
    int g = g0;
    while (g < g1) {                       // <= 2 sample-segments per block
        const int n = g >> 10;
        const int ls = g & 1023;
        const int seglen = min(LEN - ls, g1 - g);
        const int slot = bl - (8 * n) / 3; // bl - floor(1024n/384); 0..SLOTS-1

        __syncthreads();
        for (int c = 0; c < NCH; c++) {    // stage padded segment of x[n]
            const float* xc = x + (n * NCH + c) * LEN;
            for (int u = tid; u < seglen + 2 * HALO; u += 128) {
                int l = ls - HALO + u;
                Xq[c * PITCHX + u] = (l >= 0 && l < LEN) ? xc[l] : 0.0f;
            }
        }
        __syncthreads();
        for (int c = 0; c < NCH; c++) {    // per-channel 9-tap dilated sums
            const float* xb = Xq + c * PITCHX + HALO;
            float* sc = Sq + c * PITCHS;
            for (int u = tid; u < seglen; u += 128) {
                float s = ((xb[u-4*d] + xb[u-3*d]) + (xb[u-2*d] + xb[u-d]))
                        + ((xb[u] + xb[u+d]) + (xb[u+2*d] + xb[u+3*d])) + xb[u+4*d];
                sc[u] = s;
            }
        }
        __syncthreads();

        unsigned char* hrow  = hist + (warp * 32 + lane) * 36;
        unsigned char* hwarp = hist + warp * 32 * 36;

        for (int jj = 0; jj < 21; jj++) {  // each warp owns 21 kernels
            const int j = warp * 21 + jj;

            // unrank lexicographic 3-combination of 0..8 (register-only).
            // combos with first=a: C(8-a,2); with second=b2: 8-b2.
            int rem = j, a = 0;
            while (true) {
                int T = ((8 - a) * (7 - a)) >> 1;
                if (rem < T) break;
                rem -= T; a++;
            }
            int b2 = a + 1;
            while (rem >= 8 - b2) { rem -= 8 - b2; b2++; }   // FIXED (was 9-b2)
            int c2 = b2 + 1 + rem;

            const int da = (a - 4) * d, db = (b2 - 4) * d, dc = (c2 - 4) * d;
            const int* cp = ci + (i * NKER + j) * 3;
            const int ca = cp[0], cb = cp[1], cc = cp[2];
            const float* X0 = Xq + ca * PITCHX + HALO;
            const float* X1 = Xq + cb * PITCHX + HALO;
            const float* X2 = Xq + cc * PITCHX + HALO;
            const float* S0 = Sq + ca * PITCHS;
            const float* S1 = Sq + cb * PITCHS;
            const float* S2 = Sq + cc * PITCHS;
            const float* sbj = sb + j * 31;

            // hoist tree levels 1-3 into registers (warp-uniform loads)
            const float v15 = sbj[15];
            const float v7  = sbj[7],  v23 = sbj[23];
            const float v3  = sbj[3],  v11 = sbj[11];
            const float v19 = sbj[19], v27 = sbj[27];

            int vlo = 0, vhi = seglen;
            if ((i + j) & 1) {             // odd parity: interior [p, L-p)
                vlo = max(0, p - ls);
                vhi = min(seglen, LEN - p - ls);
            }
            const unsigned lim = (unsigned)max(0, vhi - vlo);

            __syncwarp();                  // prior epilogue reads done
            #pragma unroll
            for (int t = 0; t < 9; t++)
                *(unsigned*)(hrow + 4 * t) = 0u;

            for (int bse = 0; bse < seglen; bse += 128) {
                float cs[4]; int uu[4];
                if (i == 0) {              // d=1: odd tap offsets -> scalar
                    #pragma unroll
                    for (int k = 0; k < 4; k++) {
                        const int u = bse + lane + 32 * k;
                        uu[k] = u;
                        float av = ((X0[u+da] + X0[u+db]) + (X0[u+dc] + X1[u+da]))
                                 + ((X1[u+db] + X1[u+dc]) + (X2[u+da] + X2[u+db]))
                                 + X2[u+dc];
                        cs[k] = fmaf(3.0f, av, -(S0[u] + S1[u] + S2[u]));
                    }
                } else {                   // even d: float2, aligned
                    #pragma unroll
                    for (int k = 0; k < 2; k++) {
                        const int u0 = bse + 2 * lane + 64 * k;
                        float2 a0 = *(const float2*)(X0 + u0 + da);
                        float2 a1 = *(const float2*)(X0 + u0 + db);
                        float2 a2 = *(const float2*)(X0 + u0 + dc);
                        float2 a3 = *(const float2*)(X1 + u0 + da);
                        float2 a4 = *(const float2*)(X1 + u0 + db);
                        float2 a5 = *(const float2*)(X1 + u0 + dc);
                        float2 a6 = *(const float2*)(X2 + u0 + da);
                        float2 a7 = *(const float2*)(X2 + u0 + db);
                        float2 a8 = *(const float2*)(X2 + u0 + dc);
                        float2 s0 = *(const float2*)(S0 + u0);
                        float2 s1 = *(const float2*)(S1 + u0);
                        float2 s2 = *(const float2*)(S2 + u0);
                        float ax = ((a0.x+a1.x)+(a2.x+a3.x)) + ((a4.x+a5.x)+(a6.x+a7.x)) + a8.x;
                        float ay = ((a0.y+a1.y)+(a2.y+a3.y)) + ((a4.y+a5.y)+(a6.y+a7.y)) + a8.y;
                        cs[2*k]   = fmaf(3.0f, ax, -(s0.x + s1.x + s2.x));
                        cs[2*k+1] = fmaf(3.0f, ay, -(s0.y + s1.y + s2.y));
                        uu[2*k]   = u0;
                        uu[2*k+1] = u0 + 1;
                    }
                }
                // 4 independent rank chains: 3 reg levels + 2 LDS levels
                int r[4];
                #pragma unroll
                for (int k = 0; k < 4; k++) {
                    const float c = cs[k];
                    int lo = (c > v15) ? 16 : 0;
                    float t2 = (lo) ? v23 : v7;
                    lo += (c > t2) ? 8 : 0;
                    float t3a = (lo & 8) ? v11 : v3;
                    float t3b = (lo & 8) ? v27 : v19;
                    float t3  = (lo & 16) ? t3b : t3a;
                    lo += (c > t3) ? 4 : 0;
                    lo += (c > sbj[lo + 1]) ? 2 : 0;
                    lo += (c > sbj[lo]) ? 1 : 0;
                    r[k] = lo;
                }
                if ((unsigned)(uu[0] - vlo) < lim) hrow[r[0]]++;
                if ((unsigned)(uu[1] - vlo) < lim) hrow[r[1]]++;
                if ((unsigned)(uu[2] - vlo) < lim) hrow[r[2]]++;
                if ((unsigned)(uu[3] - vlo) < lim) hrow[r[3]]++;
            }

            __syncwarp();                  // all rows written
            // bin `lane` summed over the 32 private rows (diagonal walk)
            int tot = 0;
            #pragma unroll
            for (int t = 0; t < 32; t++) {
                int l = (lane + t) & 31;
                tot += hwarp[l * 36 + lane];
            }
            // suffix scan: suf[k] = sum_{r>=k} tot[r]
            int suf = tot;
            #pragma unroll
            for (int s = 1; s < 32; s <<= 1) {
                int v = __shfl_down_sync(0xffffffffu, suf, s);
                if (lane < 32 - s) suf += v;
            }
            int cnts = __shfl_down_sync(0xffffffffu, suf, 1); // lane s -> suf[s+1]
            if (lane < nf && cnts > 0) {
                int f = (sp[j * 5 + lane / 6] >> (5 * (lane % 6))) & 31;
                g_part[(((i * 64 + n) * SLOTS + slot) * NKER + j) * 32 + f] = cnts;
            }
        }
        g += seglen;
    }
}

// ---------------------------------------------------------------------------
// sum the fixed slots, scale, scatter; unwritten slots are permanently 0.
__global__ void mr_fin(float* __restrict__ out)
{
    const int j = blockIdx.x;                 // 84
    const int i = blockIdx.y;                 // 4
    const int n = blockIdx.z * 8 + threadIdx.y;
    const int f = threadIdx.x;                // 30
    const int nf = (i == 3) ? 29 : 30;
    if (f >= nf) return;

    const int base = ((i * 64 + n) * SLOTS * NKER + j) * 32 + f;
    const int ss   = NKER * 32;               // slot stride
    int c = 0;
    #pragma unroll
    for (int s = 0; s < SLOTS; s++) c += g_part[base + s * ss];

    const float inv = (((i + j) & 1) == 0)
                    ? (1.0f / 1024.0f)
                    : (1.0f / (1024.0f - 8.0f * (float)(1 << i)));
    out[n * TOTF + i * 2520 + j * nf + f] = (float)c * inv;
}

// ---------------------------------------------------------------------------
extern "C" void kernel_launch(void* const* d_in, const int* in_sizes, int n_in,
                              void* d_out, int out_size)
{
    const float* x  = (const float*)d_in[0];
    const float* b  = (const float*)d_in[1];
    const int*   ci = (const int*)d_in[2];
    float* out = (float*)d_out;

    cudaFuncSetAttribute(mr_main,
                         cudaFuncAttributePreferredSharedMemoryCarveout, 100);

    // 3 launches: capture lands on mr_main (empirical skip-5 mapping).
    mr_main<<<684, 128>>>(x, b, ci);
    mr_fin<<<dim3(NKER, 4, 8), dim3(30, 8)>>>(out);
    mr_noop<<<1, 32>>>();
}